// round 4
// baseline (speedup 1.0000x reference)
#include <cuda_runtime.h>
#include <cstdint>

#define NB 16
#define NC 64          // C_IN == C_OUT == 64
#define VIN 40962
#define VOUT 163842
#define G1 321         // ceil(VIN/128)  stage-1 blocks per batch
#define G2 2561        // ceil(VOUT/64)  stage-2 blocks per batch

typedef unsigned long long ull;

// Double-buffered y: stage1(b) writes g_y[b&1], stage2(b) reads g_y[b&1].
// 2 x 10.5 MB -> L2-resident; DRAM never sees y in steady state.
__device__ float g_y[2][(size_t)VIN * NC];
__device__ int g_idx_is64;

struct S1 { float xs[64][128]; float ws[64][64]; };   // 48 KB exactly
struct S2 { float t[64][65];   float bs[64];    };    // 16.9 KB

// ---------------------------------------------------------------------------
// Fused pipeline kernel. Blocks [0, nS1) run stage1 for batch b1;
// blocks [nS1, nS1+G2) run stage2 for batch b2. b1/b2 touch different y
// buffers, so no intra-launch ordering is needed; stream order between
// launches provides the stage1(b) -> stage2(b) dependency.
// ---------------------------------------------------------------------------
__global__ __launch_bounds__(256)
void fused_kernel(int b1, int b2,
                  const float* __restrict__ x,
                  const float* __restrict__ W,
                  const void* __restrict__ idx_raw,
                  const float* __restrict__ bias,
                  float* __restrict__ out) {
    __shared__ union { S1 s1; S2 s2; } sm;
    const int tid = threadIdx.x;
    const int nS1 = (b1 >= 0) ? G1 : 0;

    if ((int)blockIdx.x < nS1) {
        // =================== stage 1: y[u,o] = sum_c x[b1,c,u] W[o,c] =======
        if (b1 == 0 && blockIdx.x == 0 && tid == 0) {
            // idx dtype detect (int64 -> odd 32-bit words are all zero)
            const int* p = (const int*)idx_raw;
            int all_odd_zero = 1;
#pragma unroll
            for (int k = 0; k < 8; k++)
                if (p[2 * k + 1] != 0) all_odd_zero = 0;
            g_idx_is64 = all_odd_zero;
        }

        float (*xs)[128] = sm.s1.xs;
        float (*ws)[64]  = sm.s1.ws;
        const int u0 = blockIdx.x * 128;

        // W tile [o][c] as-is: coalesced load, no transpose needed.
#pragma unroll
        for (int i = tid; i < 64 * 64; i += 256)
            ((float*)ws)[i] = W[i];

        // x tile [c][u] (float2; rows only 8B-aligned since VIN is even)
        const float* xb = x + (size_t)b1 * NC * VIN + u0;
        if (u0 + 128 <= VIN) {
#pragma unroll
            for (int i = tid; i < 64 * 64; i += 256) {
                int c = i >> 6, j = i & 63;
                float2 v = __ldcs((const float2*)(xb + (size_t)c * VIN + j * 2));
                *(float2*)&xs[c][j * 2] = v;
            }
        } else {
            for (int i = tid; i < 64 * 128; i += 256) {
                int c = i >> 7, u = i & 127;
                xs[c][u] = (u0 + u < VIN) ? __ldcs(xb + (size_t)c * VIN + u) : 0.0f;
            }
        }
        __syncthreads();

        const int uq = tid & 31;   // u quad: u = uq*4 + 0..3
        const int og = tid >> 5;   // o octet (warp-uniform): o = og*8 + 0..7

        // acc[p][j]: packed f32x2 over u-pair p (u = uq*4+2p, +2p+1), o = og*8+j
        ull acc[2][8];
#pragma unroll
        for (int p = 0; p < 2; p++)
#pragma unroll
            for (int j = 0; j < 8; j++) acc[p][j] = 0ull;

#pragma unroll 16
        for (int c = 0; c < 64; c++) {
            double2 xv = *(const double2*)&xs[c][uq * 4];   // 2 packed u-pairs
            ull xp0 = __double_as_longlong(xv.x);
            ull xp1 = __double_as_longlong(xv.y);
#pragma unroll
            for (int j = 0; j < 8; j++) {
                float w = ws[og * 8 + j][c];                // uniform broadcast
                ull wp;
                asm("mov.b64 %0, {%1, %1};" : "=l"(wp) : "f"(w));
                asm("fma.rn.f32x2 %0, %1, %2, %0;" : "+l"(acc[0][j]) : "l"(xp0), "l"(wp));
                asm("fma.rn.f32x2 %0, %1, %2, %0;" : "+l"(acc[1][j]) : "l"(xp1), "l"(wp));
            }
        }

        float* yb = g_y[b1 & 1];
#pragma unroll
        for (int du = 0; du < 4; du++) {
            int ug = u0 + uq * 4 + du;
            if (ug < VIN) {
                const int p  = du >> 1;
                const int hi = du & 1;
                union { ull u; float2 f; } cv;
                float r[8];
#pragma unroll
                for (int j = 0; j < 8; j++) {
                    cv.u = acc[p][j];
                    r[j] = hi ? cv.f.y : cv.f.x;
                }
                float* row = &yb[(size_t)ug * NC + og * 8];
                *(float4*)row       = make_float4(r[0], r[1], r[2], r[3]);
                *(float4*)(row + 4) = make_float4(r[4], r[5], r[6], r[7]);
            }
        }
    } else {
        // =================== stage 2: out[b2,o,v] = mean + bias =============
        float (*t)[65] = sm.s2.t;
        float* bs      = sm.s2.bs;

        const int v0 = ((int)blockIdx.x - nS1) * 64;
        const int is64 = g_idx_is64;

        if (tid < 64) bs[tid] = bias[tid];

        const float* yb = g_y[b2 & 1];

        {
            const int vl = tid >> 2;
            const int q  = tid & 3;
            const int v  = v0 + vl;
            if (v < VOUT) {
                long long i0, i1;
                if (is64) {
                    const long long* p = (const long long*)idx_raw + (size_t)v * 2;
                    i0 = p[0]; i1 = p[1];
                } else {
                    const int* p = (const int*)idx_raw + (size_t)v * 2;
                    i0 = p[0]; i1 = p[1];
                }
                i0 = i0 < 0 ? 0 : (i0 >= VIN ? VIN - 1 : i0);
                i1 = i1 < 0 ? 0 : (i1 >= VIN ? VIN - 1 : i1);
                const float* r0 = yb + (size_t)i0 * NC;
                const float* r1 = yb + (size_t)i1 * NC;
#pragma unroll
                for (int it = 0; it < 4; it++) {
                    int c = it * 16 + q * 4;
                    float4 a  = *(const float4*)&r0[c];
                    float4 c2 = *(const float4*)&r1[c];
                    t[vl][c + 0] = 0.5f * (a.x + c2.x);
                    t[vl][c + 1] = 0.5f * (a.y + c2.y);
                    t[vl][c + 2] = 0.5f * (a.z + c2.z);
                    t[vl][c + 3] = 0.5f * (a.w + c2.w);
                }
            }
        }
        __syncthreads();

        {
            const int lv = tid & 63;
            const int og = tid >> 6;
            const int vg = v0 + lv;
            if (vg < VOUT) {
                float* ob = out + (size_t)b2 * NC * VOUT + (size_t)vg;
#pragma unroll
                for (int i = 0; i < 16; i++) {
                    int o = og * 16 + i;
                    __stcs(&ob[(size_t)o * VOUT], t[lv][o] + bs[o]);
                }
            }
        }
    }
}

// ---------------------------------------------------------------------------
extern "C" void kernel_launch(void* const* d_in, const int* in_sizes, int n_in,
                              void* d_out, int out_size) {
    const float* x = nullptr;
    const void*  idx = nullptr;
    const float* W = nullptr;
    const float* bias = nullptr;
    for (int i = 0; i < n_in; i++) {
        switch (in_sizes[i]) {
            case 41945088: x    = (const float*)d_in[i]; break;  // 16*64*40962
            case 327684:   idx  = d_in[i];               break;  // 163842*2
            case 4096:     W    = (const float*)d_in[i]; break;  // 64*64
            case 64:       bias = (const float*)d_in[i]; break;  // 64
            default: break;
        }
    }
    float* out = (float*)d_out;
    (void)out_size;

    // Software pipeline: launch i = stage1(batch i) + stage2(batch i-1).
    for (int i = 0; i <= NB; i++) {
        int b1 = (i < NB) ? i : -1;
        int b2 = i - 1;
        int g  = ((b1 >= 0) ? G1 : 0) + ((b2 >= 0) ? G2 : 0);
        fused_kernel<<<g, 256>>>(b1, b2, x, W, idx, bias, out);
    }
}

// round 5
// speedup vs baseline: 1.4912x; 1.4912x over previous
#include <cuda_runtime.h>
#include <cuda_fp16.h>
#include <cstdint>

#define NB 16
#define NC 64          // C_IN == C_OUT == 64
#define VIN 40962
#define VOUT 163842

typedef unsigned long long ull;

// Scratch: y[b][u][o] in fp16, rows of 128B. 16*40962*64*2 = 84 MB (fits L2).
__device__ __half g_y[(size_t)NB * VIN * NC];
// W transposed once: g_wt[c*64+o] = W[o*64+c]
__device__ float g_wt[NC * NC];
// 1 if idx buffer is int64, 0 if int32.
__device__ int g_idx_is64;

// ---------------------------------------------------------------------------
// Prep: detect idx dtype (int64 has zero high words) + transpose W once.
// ---------------------------------------------------------------------------
__global__ void prep_kernel(const float* __restrict__ W,
                            const int* __restrict__ idx32) {
    const int tid = threadIdx.x;
    if (tid == 0) {
        int all_odd_zero = 1;
#pragma unroll
        for (int k = 0; k < 8; k++)
            if (idx32[2 * k + 1] != 0) all_odd_zero = 0;
        g_idx_is64 = all_odd_zero;
    }
    for (int i = tid; i < NC * NC; i += blockDim.x) {
        int c = i >> 6, o = i & 63;
        g_wt[c * 64 + o] = W[o * 64 + c];
    }
}

// ---------------------------------------------------------------------------
// Stage 1: y[b,u,o] = sum_c x[b,c,u] * W[o,c]   (fp32 math, fp16 store)
// 256 threads, tile 128u x 64o; each thread 4u x 8o via packed f32x2 FMA.
// ---------------------------------------------------------------------------
__global__ __launch_bounds__(256)
void stage1_gemm(const float* __restrict__ x) {
    __shared__ float xs[64][128];   // [c][u]  32 KB
    __shared__ float wt[64][64];    // [c][o]  16 KB

    const int b   = blockIdx.y;
    const int u0  = blockIdx.x * 128;
    const int tid = threadIdx.x;
    const int uq  = tid & 31;       // u quad:  u = uq*4 + 0..3
    const int og  = tid >> 5;       // o octet (warp-uniform): o = og*8 + 0..7

#pragma unroll
    for (int i = tid; i < NC * NC; i += 256)
        ((float*)wt)[i] = g_wt[i];

    const float* xb = x + (size_t)b * NC * VIN + u0;
    if (u0 + 128 <= VIN) {
#pragma unroll
        for (int i = tid; i < 64 * 64; i += 256) {
            int c = i >> 6, j = i & 63;
            float2 v = __ldcs((const float2*)(xb + (size_t)c * VIN + j * 2));
            *(float2*)&xs[c][j * 2] = v;
        }
    } else {
        for (int i = tid; i < 64 * 128; i += 256) {
            int c = i >> 7, u = i & 127;
            xs[c][u] = (u0 + u < VIN) ? __ldcs(xb + (size_t)c * VIN + u) : 0.0f;
        }
    }
    __syncthreads();

    // acc[p][j]: packed f32x2 over u-pair p (u = uq*4+2p, 2p+1), o = og*8+j
    ull acc[2][8];
#pragma unroll
    for (int p = 0; p < 2; p++)
#pragma unroll
        for (int j = 0; j < 8; j++) acc[p][j] = 0ull;

#pragma unroll 16
    for (int c = 0; c < 64; c++) {
        double2 xv = *(const double2*)&xs[c][uq * 4];   // 2 packed u-pairs
        ull xp0 = __double_as_longlong(xv.x);
        ull xp1 = __double_as_longlong(xv.y);
        float4 w0 = *(const float4*)&wt[c][og * 8];     // warp-uniform broadcast
        float4 w1 = *(const float4*)&wt[c][og * 8 + 4];
        float wf[8] = {w0.x, w0.y, w0.z, w0.w, w1.x, w1.y, w1.z, w1.w};
#pragma unroll
        for (int j = 0; j < 8; j++) {
            ull wp;
            asm("mov.b64 %0, {%1, %1};" : "=l"(wp) : "f"(wf[j]));
            asm("fma.rn.f32x2 %0, %1, %2, %0;" : "+l"(acc[0][j]) : "l"(xp0), "l"(wp));
            asm("fma.rn.f32x2 %0, %1, %2, %0;" : "+l"(acc[1][j]) : "l"(xp1), "l"(wp));
        }
    }

    // Epilogue: convert to fp16, one 16B store per (u, 8o).
    __half* yb = g_y + (size_t)b * VIN * NC;
#pragma unroll
    for (int du = 0; du < 4; du++) {
        int ug = u0 + uq * 4 + du;
        if (ug < VIN) {
            const int p  = du >> 1;
            const int hi = du & 1;
            union { ull u; float2 f; } cv;
            float r[8];
#pragma unroll
            for (int j = 0; j < 8; j++) {
                cv.u = acc[p][j];
                r[j] = hi ? cv.f.y : cv.f.x;
            }
            union { __half2 h[4]; uint4 v; } pk;
#pragma unroll
            for (int k = 0; k < 4; k++)
                pk.h[k] = __floats2half2_rn(r[2 * k], r[2 * k + 1]);
            *(uint4*)&yb[(size_t)ug * NC + og * 8] = pk.v;
        }
    }
}

// ---------------------------------------------------------------------------
// Stage 2: out[b,o,v] = 0.5*(y[b,i0,o] + y[b,i1,o]) + bias[o]   (fp32 math)
// 256 threads, 64-vertex tile; 4 threads/vertex, 2x uint4 (16 halves) each/row.
// ---------------------------------------------------------------------------
__global__ __launch_bounds__(256)
void stage2_gather(const void* __restrict__ idx_raw,
                   const float* __restrict__ bias,
                   float* __restrict__ out) {
    __shared__ float t[64][65];
    __shared__ float bs[64];

    const int b   = blockIdx.y;
    const int v0  = blockIdx.x * 64;
    const int tid = threadIdx.x;
    const int is64 = g_idx_is64;

    if (tid < 64) bs[tid] = bias[tid];

    const __half* yb = g_y + (size_t)b * VIN * NC;

    {
        const int vl = tid >> 2;
        const int q  = tid & 3;
        const int v  = v0 + vl;
        if (v < VOUT) {
            long long i0, i1;
            if (is64) {
                const long long* p = (const long long*)idx_raw + (size_t)v * 2;
                i0 = p[0]; i1 = p[1];
            } else {
                const int* p = (const int*)idx_raw + (size_t)v * 2;
                i0 = p[0]; i1 = p[1];
            }
            i0 = i0 < 0 ? 0 : (i0 >= VIN ? VIN - 1 : i0);
            i1 = i1 < 0 ? 0 : (i1 >= VIN ? VIN - 1 : i1);
            const __half* r0 = yb + (size_t)i0 * NC;
            const __half* r1 = yb + (size_t)i1 * NC;
#pragma unroll
            for (int it = 0; it < 2; it++) {
                int c = q * 16 + it * 8;                 // 8 halves per load
                union { uint4 v; __half2 h[4]; } a, d;
                a.v = *(const uint4*)(r0 + c);
                d.v = *(const uint4*)(r1 + c);
#pragma unroll
                for (int k = 0; k < 4; k++) {
                    float2 fa = __half22float2(a.h[k]);
                    float2 fd = __half22float2(d.h[k]);
                    t[vl][c + 2 * k + 0] = 0.5f * (fa.x + fd.x);
                    t[vl][c + 2 * k + 1] = 0.5f * (fa.y + fd.y);
                }
            }
        }
    }
    __syncthreads();

    // Write phase: coalesced along v; streaming stores (out never re-read).
    {
        const int lv = tid & 63;
        const int og = tid >> 6;
        const int vg = v0 + lv;
        if (vg < VOUT) {
            float* ob = out + (size_t)b * NC * VOUT + (size_t)vg;
#pragma unroll
            for (int i = 0; i < 16; i++) {
                int o = og * 16 + i;
                __stcs(&ob[(size_t)o * VOUT], t[lv][o] + bs[o]);
            }
        }
    }
}

// ---------------------------------------------------------------------------
extern "C" void kernel_launch(void* const* d_in, const int* in_sizes, int n_in,
                              void* d_out, int out_size) {
    const float* x = nullptr;
    const void*  idx = nullptr;
    const float* W = nullptr;
    const float* bias = nullptr;
    for (int i = 0; i < n_in; i++) {
        switch (in_sizes[i]) {
            case 41945088: x    = (const float*)d_in[i]; break;  // 16*64*40962
            case 327684:   idx  = d_in[i];               break;  // 163842*2
            case 4096:     W    = (const float*)d_in[i]; break;  // 64*64
            case 64:       bias = (const float*)d_in[i]; break;  // 64
            default: break;
        }
    }
    float* out = (float*)d_out;
    (void)out_size;

    prep_kernel<<<1, 256>>>(W, (const int*)idx);

    dim3 g1((VIN + 127) / 128, NB);
    stage1_gemm<<<g1, 256>>>(x);

    dim3 g2((VOUT + 63) / 64, NB);
    stage2_gather<<<g2, 256>>>(idx, bias, out);
}

// round 6
// speedup vs baseline: 1.6435x; 1.1022x over previous
#include <cuda_runtime.h>
#include <cuda_fp16.h>
#include <cstdint>

#define NB 16
#define NC 64          // C_IN == C_OUT == 64
#define VIN 40962
#define VOUT 163842

// Scratch: y[b][u][o] in fp16, rows of 128B. 84 MB (mostly L2-resident).
__device__ __half g_y[(size_t)NB * VIN * NC];
// 1 if idx buffer is int64, 0 if int32.
__device__ int g_idx_is64;

static __device__ __forceinline__ uint32_t pack_h2(float a, float b) {
    __half2 h = __floats2half2_rn(a, b);
    return *(uint32_t*)&h;
}

static __device__ __forceinline__ void mma16816(float* d, const uint32_t* a,
                                                uint32_t b0, uint32_t b1) {
    asm volatile(
        "mma.sync.aligned.m16n8k16.row.col.f32.f16.f16.f32 "
        "{%0,%1,%2,%3}, {%4,%5,%6,%7}, {%8,%9}, {%0,%1,%2,%3};"
        : "+f"(d[0]), "+f"(d[1]), "+f"(d[2]), "+f"(d[3])
        : "r"(a[0]), "r"(a[1]), "r"(a[2]), "r"(a[3]), "r"(b0), "r"(b1));
}

// ---------------------------------------------------------------------------
// Stage 1: y[b,u,o] = sum_c x[b,c,u] * W[o,c]  via m16n8k16 HMMA, f32 accum.
// 128 threads, tile 128u x 64o x 64c. Warp w: u rows [w*32, w*32+32).
// smem xs[u][cp] holds half2(x[2cp][u], x[2cp+1][u])  -> A fragment = LDS.32
// smem wb[o][cp] holds half2(W[o][2cp], W[o][2cp+1])  -> B fragment = LDS.32
// ---------------------------------------------------------------------------
__global__ __launch_bounds__(128)
void stage1_mma(const float* __restrict__ x, const float* __restrict__ W,
                const void* __restrict__ idx_raw) {
    __shared__ uint32_t xs[128][33];   // 16.9 KB (row stride 33 words: odd -> low conflicts)
    __shared__ uint32_t wb[64][33];    // 8.45 KB

    const int b   = blockIdx.y;
    const int u0  = blockIdx.x * 128;
    const int tid = threadIdx.x;

    if (b == 0 && blockIdx.x == 0 && tid == 0) {
        // idx dtype detect: int64 data has all-zero odd 32-bit words.
        const int* p = (const int*)idx_raw;
        int all_odd_zero = 1;
#pragma unroll
        for (int k = 0; k < 8; k++)
            if (p[2 * k + 1] != 0) all_odd_zero = 0;
        g_idx_is64 = all_odd_zero;
    }

    // ---- fill W tile (fp16 packed pairs along c) ----
    for (int i = tid; i < 64 * 32; i += 128) {
        int o = i >> 5, cp = i & 31;
        float2 wv = *(const float2*)&W[o * 64 + cp * 2];
        wb[o][cp] = pack_h2(wv.x, wv.y);
    }

    // ---- fill x tile ----
    const float* xb = x + (size_t)b * NC * VIN + u0;
    if (u0 + 128 <= VIN) {
#pragma unroll
        for (int i = tid; i < 32 * 64; i += 128) {
            int cp = i >> 6, up = i & 63;
            const float* p0 = xb + (size_t)(2 * cp) * VIN;
            float2 v0 = __ldcs((const float2*)(p0 + 2 * up));
            float2 v1 = __ldcs((const float2*)(p0 + VIN + 2 * up));
            xs[2 * up][cp]     = pack_h2(v0.x, v1.x);
            xs[2 * up + 1][cp] = pack_h2(v0.y, v1.y);
        }
    } else {
        for (int i = tid; i < 32 * 64; i += 128) {
            int cp = i >> 6, up = i & 63;
            const float* p0 = xb + (size_t)(2 * cp) * VIN;
            int uA = 2 * up, uB = 2 * up + 1;
            float a0 = (u0 + uA < VIN) ? p0[uA] : 0.0f;
            float a1 = (u0 + uA < VIN) ? p0[VIN + uA] : 0.0f;
            float b0 = (u0 + uB < VIN) ? p0[uB] : 0.0f;
            float b1 = (u0 + uB < VIN) ? p0[VIN + uB] : 0.0f;
            xs[uA][cp] = pack_h2(a0, a1);
            xs[uB][cp] = pack_h2(b0, b1);
        }
    }
    __syncthreads();

    // ---- compute: per warp 32u x 64o, k=64 ----
    const int lane = tid & 31, wid = tid >> 5;
    const int g = lane >> 2, t = lane & 3;
    const int ub = wid * 32;

    float acc[2][8][4];
#pragma unroll
    for (int mt = 0; mt < 2; mt++)
#pragma unroll
        for (int nt = 0; nt < 8; nt++)
#pragma unroll
            for (int r = 0; r < 4; r++) acc[mt][nt][r] = 0.0f;

#pragma unroll
    for (int kt = 0; kt < 4; kt++) {
        uint32_t a[2][4];
#pragma unroll
        for (int mt = 0; mt < 2; mt++) {
            int r = ub + mt * 16;
            a[mt][0] = xs[r + g][kt * 8 + t];
            a[mt][1] = xs[r + 8 + g][kt * 8 + t];
            a[mt][2] = xs[r + g][kt * 8 + 4 + t];
            a[mt][3] = xs[r + 8 + g][kt * 8 + 4 + t];
        }
#pragma unroll
        for (int nt = 0; nt < 8; nt++) {
            uint32_t b0 = wb[nt * 8 + g][kt * 8 + t];
            uint32_t b1 = wb[nt * 8 + g][kt * 8 + 4 + t];
            mma16816(acc[0][nt], a[0], b0, b1);
            mma16816(acc[1][nt], a[1], b0, b1);
        }
    }

    // ---- epilogue: stage fp16 result in smem (reuse xs), then coalesced STG ----
    __syncthreads();   // everyone done reading xs
    uint32_t* ys = (uint32_t*)xs;   // ys[u] row = 32 half2 words, stride 33
#pragma unroll
    for (int mt = 0; mt < 2; mt++) {
        int r0 = ub + mt * 16 + g;
#pragma unroll
        for (int nt = 0; nt < 8; nt++) {
            ys[r0 * 33 + nt * 4 + t]       = pack_h2(acc[mt][nt][0], acc[mt][nt][1]);
            ys[(r0 + 8) * 33 + nt * 4 + t] = pack_h2(acc[mt][nt][2], acc[mt][nt][3]);
        }
    }
    __syncthreads();

    __half* yb = g_y + (size_t)b * VIN * NC;
#pragma unroll
    for (int i = tid; i < 128 * 8; i += 128) {
        int u = i >> 3, q = i & 7;
        if (u0 + u < VIN) {
            const uint32_t* row = ys + u * 33 + q * 4;
            uint4 v = make_uint4(row[0], row[1], row[2], row[3]);
            *(uint4*)&yb[(size_t)(u0 + u) * NC + q * 8] = v;
        }
    }
}

// ---------------------------------------------------------------------------
// Stage 2: out[b,o,v] = 0.5*(y[b,i0,o] + y[b,i1,o]) + bias[o]   (fp32 math)
// ---------------------------------------------------------------------------
__global__ __launch_bounds__(256)
void stage2_gather(const void* __restrict__ idx_raw,
                   const float* __restrict__ bias,
                   float* __restrict__ out) {
    __shared__ float t[64][65];
    __shared__ float bs[64];

    const int b   = blockIdx.y;
    const int v0  = blockIdx.x * 64;
    const int tid = threadIdx.x;
    const int is64 = g_idx_is64;

    if (tid < 64) bs[tid] = bias[tid];

    const __half* yb = g_y + (size_t)b * VIN * NC;

    {
        const int vl = tid >> 2;
        const int q  = tid & 3;
        const int v  = v0 + vl;
        if (v < VOUT) {
            long long i0, i1;
            if (is64) {
                const long long* p = (const long long*)idx_raw + (size_t)v * 2;
                i0 = p[0]; i1 = p[1];
            } else {
                const int* p = (const int*)idx_raw + (size_t)v * 2;
                i0 = p[0]; i1 = p[1];
            }
            i0 = i0 < 0 ? 0 : (i0 >= VIN ? VIN - 1 : i0);
            i1 = i1 < 0 ? 0 : (i1 >= VIN ? VIN - 1 : i1);
            const __half* r0 = yb + (size_t)i0 * NC;
            const __half* r1 = yb + (size_t)i1 * NC;
#pragma unroll
            for (int it = 0; it < 2; it++) {
                int c = q * 16 + it * 8;
                union { uint4 v; __half2 h[4]; } a, d;
                a.v = *(const uint4*)(r0 + c);
                d.v = *(const uint4*)(r1 + c);
#pragma unroll
                for (int k = 0; k < 4; k++) {
                    float2 fa = __half22float2(a.h[k]);
                    float2 fd = __half22float2(d.h[k]);
                    t[vl][c + 2 * k + 0] = 0.5f * (fa.x + fd.x);
                    t[vl][c + 2 * k + 1] = 0.5f * (fa.y + fd.y);
                }
            }
        }
    }
    __syncthreads();

    {
        const int lv = tid & 63;
        const int og = tid >> 6;
        const int vg = v0 + lv;
        if (vg < VOUT) {
            float* ob = out + (size_t)b * NC * VOUT + (size_t)vg;
#pragma unroll
            for (int i = 0; i < 16; i++) {
                int o = og * 16 + i;
                __stcs(&ob[(size_t)o * VOUT], t[lv][o] + bs[o]);
            }
        }
    }
}

// ---------------------------------------------------------------------------
extern "C" void kernel_launch(void* const* d_in, const int* in_sizes, int n_in,
                              void* d_out, int out_size) {
    const float* x = nullptr;
    const void*  idx = nullptr;
    const float* W = nullptr;
    const float* bias = nullptr;
    for (int i = 0; i < n_in; i++) {
        switch (in_sizes[i]) {
            case 41945088: x    = (const float*)d_in[i]; break;  // 16*64*40962
            case 327684:   idx  = d_in[i];               break;  // 163842*2
            case 4096:     W    = (const float*)d_in[i]; break;  // 64*64
            case 64:       bias = (const float*)d_in[i]; break;  // 64
            default: break;
        }
    }
    float* out = (float*)d_out;
    (void)out_size;

    dim3 g1((VIN + 127) / 128, NB);
    stage1_mma<<<g1, 128>>>(x, W, idx);

    dim3 g2((VOUT + 63) / 64, NB);
    stage2_gather<<<g2, 256>>>(idx, bias, out);
}

// round 7
// speedup vs baseline: 1.6478x; 1.0026x over previous
#include <cuda_runtime.h>
#include <cuda_fp16.h>
#include <cstdint>

#define NB 16
#define NC 64          // C_IN == C_OUT == 64
#define VIN 40962
#define VOUT 163842

// Scratch: y[b][u][o] in fp16, rows of 128B. 84 MB (mostly L2-resident).
__device__ __half g_y[(size_t)NB * VIN * NC];
// 1 if idx buffer is int64, 0 if int32.
__device__ int g_idx_is64;

static __device__ __forceinline__ uint32_t pack_h2(float a, float b) {
    __half2 h = __floats2half2_rn(a, b);
    return *(uint32_t*)&h;
}

static __device__ __forceinline__ void mma16816(float* d, const uint32_t* a,
                                                uint32_t b0, uint32_t b1) {
    asm volatile(
        "mma.sync.aligned.m16n8k16.row.col.f32.f16.f16.f32 "
        "{%0,%1,%2,%3}, {%4,%5,%6,%7}, {%8,%9}, {%0,%1,%2,%3};"
        : "+f"(d[0]), "+f"(d[1]), "+f"(d[2]), "+f"(d[3])
        : "r"(a[0]), "r"(a[1]), "r"(a[2]), "r"(a[3]), "r"(b0), "r"(b1));
}

// ---------------------------------------------------------------------------
// Stage 1 (unchanged from R6): y = x^T W^T via m16n8k16 HMMA, f32 accum.
// ---------------------------------------------------------------------------
__global__ __launch_bounds__(128)
void stage1_mma(const float* __restrict__ x, const float* __restrict__ W,
                const void* __restrict__ idx_raw) {
    __shared__ uint32_t xs[128][33];
    __shared__ uint32_t wb[64][33];

    const int b   = blockIdx.y;
    const int u0  = blockIdx.x * 128;
    const int tid = threadIdx.x;

    if (b == 0 && blockIdx.x == 0 && tid == 0) {
        const int* p = (const int*)idx_raw;
        int all_odd_zero = 1;
#pragma unroll
        for (int k = 0; k < 8; k++)
            if (p[2 * k + 1] != 0) all_odd_zero = 0;
        g_idx_is64 = all_odd_zero;
    }

    for (int i = tid; i < 64 * 32; i += 128) {
        int o = i >> 5, cp = i & 31;
        float2 wv = *(const float2*)&W[o * 64 + cp * 2];
        wb[o][cp] = pack_h2(wv.x, wv.y);
    }

    const float* xb = x + (size_t)b * NC * VIN + u0;
    if (u0 + 128 <= VIN) {
#pragma unroll
        for (int i = tid; i < 32 * 64; i += 128) {
            int cp = i >> 6, up = i & 63;
            const float* p0 = xb + (size_t)(2 * cp) * VIN;
            float2 v0 = __ldcs((const float2*)(p0 + 2 * up));
            float2 v1 = __ldcs((const float2*)(p0 + VIN + 2 * up));
            xs[2 * up][cp]     = pack_h2(v0.x, v1.x);
            xs[2 * up + 1][cp] = pack_h2(v0.y, v1.y);
        }
    } else {
        for (int i = tid; i < 32 * 64; i += 128) {
            int cp = i >> 6, up = i & 63;
            const float* p0 = xb + (size_t)(2 * cp) * VIN;
            int uA = 2 * up, uB = 2 * up + 1;
            float a0 = (u0 + uA < VIN) ? p0[uA] : 0.0f;
            float a1 = (u0 + uA < VIN) ? p0[VIN + uA] : 0.0f;
            float b0 = (u0 + uB < VIN) ? p0[uB] : 0.0f;
            float b1 = (u0 + uB < VIN) ? p0[VIN + uB] : 0.0f;
            xs[uA][cp] = pack_h2(a0, a1);
            xs[uB][cp] = pack_h2(b0, b1);
        }
    }
    __syncthreads();

    const int lane = tid & 31, wid = tid >> 5;
    const int g = lane >> 2, t = lane & 3;
    const int ub = wid * 32;

    float acc[2][8][4];
#pragma unroll
    for (int mt = 0; mt < 2; mt++)
#pragma unroll
        for (int nt = 0; nt < 8; nt++)
#pragma unroll
            for (int r = 0; r < 4; r++) acc[mt][nt][r] = 0.0f;

#pragma unroll
    for (int kt = 0; kt < 4; kt++) {
        uint32_t a[2][4];
#pragma unroll
        for (int mt = 0; mt < 2; mt++) {
            int r = ub + mt * 16;
            a[mt][0] = xs[r + g][kt * 8 + t];
            a[mt][1] = xs[r + 8 + g][kt * 8 + t];
            a[mt][2] = xs[r + g][kt * 8 + 4 + t];
            a[mt][3] = xs[r + 8 + g][kt * 8 + 4 + t];
        }
#pragma unroll
        for (int nt = 0; nt < 8; nt++) {
            uint32_t b0 = wb[nt * 8 + g][kt * 8 + t];
            uint32_t b1 = wb[nt * 8 + g][kt * 8 + 4 + t];
            mma16816(acc[0][nt], a[0], b0, b1);
            mma16816(acc[1][nt], a[1], b0, b1);
        }
    }

    __syncthreads();
    uint32_t* ys = (uint32_t*)xs;
#pragma unroll
    for (int mt = 0; mt < 2; mt++) {
        int r0 = ub + mt * 16 + g;
#pragma unroll
        for (int nt = 0; nt < 8; nt++) {
            ys[r0 * 33 + nt * 4 + t]       = pack_h2(acc[mt][nt][0], acc[mt][nt][1]);
            ys[(r0 + 8) * 33 + nt * 4 + t] = pack_h2(acc[mt][nt][2], acc[mt][nt][3]);
        }
    }
    __syncthreads();

    __half* yb = g_y + (size_t)b * VIN * NC;
#pragma unroll
    for (int i = tid; i < 128 * 8; i += 128) {
        int u = i >> 3, q = i & 7;
        if (u0 + u < VIN) {
            const uint32_t* row = ys + u * 33 + q * 4;
            uint4 v = make_uint4(row[0], row[1], row[2], row[3]);
            *(uint4*)&yb[(size_t)(u0 + u) * NC + q * 8] = v;
        }
    }
}

// ---------------------------------------------------------------------------
// Stage 2 v2: out[b,o,v] = 0.5*(y[i0]+y[i1]) + bias[o]
// Gather: warp handles 4 vertices/iter; 8 lanes x 16B = full 128B y-row per
//         LDG.128 -> 2 wavefronts/vertex (floor). fp32 avg in registers.
// Write:  warp per o-row, float2 along v -> 1 STG.64 instr covers 64 v.
// ---------------------------------------------------------------------------
__global__ __launch_bounds__(256)
void stage2_gather(const void* __restrict__ idx_raw,
                   const float* __restrict__ bias,
                   float* __restrict__ out) {
    __shared__ float t[64][65];
    __shared__ float bs[64];

    const int b    = blockIdx.y;
    const int v0   = blockIdx.x * 64;
    const int tid  = threadIdx.x;
    const int lane = tid & 31;
    const int w    = tid >> 5;
    const int is64 = g_idx_is64;

    if (tid < 64) bs[tid] = bias[tid];

    const __half* yb = g_y + (size_t)b * VIN * NC;

    // ---- gather: 2 iters x 4 vertices per warp = 8 vertices/warp ----
    const int g = lane >> 3;      // vertex within quad
    const int s = lane & 7;       // 16B chunk within 128B row
#pragma unroll
    for (int it = 0; it < 2; it++) {
        const int vl = w * 8 + it * 4 + g;
        const int v  = v0 + vl;
        if (v < VOUT) {
            long long i0, i1;
            if (is64) {
                longlong2 p = *((const longlong2*)idx_raw + v);
                i0 = p.x; i1 = p.y;
            } else {
                int2 p = *((const int2*)idx_raw + v);
                i0 = p.x; i1 = p.y;
            }
            i0 = i0 < 0 ? 0 : (i0 >= VIN ? VIN - 1 : i0);
            i1 = i1 < 0 ? 0 : (i1 >= VIN ? VIN - 1 : i1);
            union { uint4 u; __half2 h[4]; } A, B;
            A.u = *(const uint4*)(yb + (size_t)i0 * NC + s * 8);
            B.u = *(const uint4*)(yb + (size_t)i1 * NC + s * 8);
            float* trow = &t[vl][s * 8];
#pragma unroll
            for (int k = 0; k < 4; k++) {
                float2 fa = __half22float2(A.h[k]);
                float2 fb = __half22float2(B.h[k]);
                trow[2 * k + 0] = 0.5f * (fa.x + fb.x);
                trow[2 * k + 1] = 0.5f * (fa.y + fb.y);
            }
        }
    }
    __syncthreads();

    // ---- write: warp w covers o in {w, w+8, ..., w+56}; lane = v-pair ----
    {
        const int vg = v0 + 2 * lane;
        if (vg + 1 < VOUT + 1 && vg < VOUT) {   // VOUT even, pairs atomic
            float* ob = out + (size_t)b * NC * VOUT + vg;
#pragma unroll
            for (int j = 0; j < 8; j++) {
                const int o = w + 8 * j;
                const float bo = bs[o];
                float2 r = make_float2(t[2 * lane][o] + bo,
                                       t[2 * lane + 1][o] + bo);
                __stcs((float2*)(ob + (size_t)o * VOUT), r);
            }
        }
    }
}

// ---------------------------------------------------------------------------
extern "C" void kernel_launch(void* const* d_in, const int* in_sizes, int n_in,
                              void* d_out, int out_size) {
    const float* x = nullptr;
    const void*  idx = nullptr;
    const float* W = nullptr;
    const float* bias = nullptr;
    for (int i = 0; i < n_in; i++) {
        switch (in_sizes[i]) {
            case 41945088: x    = (const float*)d_in[i]; break;  // 16*64*40962
            case 327684:   idx  = d_in[i];               break;  // 163842*2
            case 4096:     W    = (const float*)d_in[i]; break;  // 64*64
            case 64:       bias = (const float*)d_in[i]; break;  // 64
            default: break;
        }
    }
    float* out = (float*)d_out;
    (void)out_size;

    dim3 g1((VIN + 127) / 128, NB);
    stage1_mma<<<g1, 128>>>(x, W, idx);

    dim3 g2((VOUT + 63) / 64, NB);
    stage2_gather<<<g2, 256>>>(idx, bias, out);
}